// round 14
// baseline (speedup 1.0000x reference)
#include <cuda_runtime.h>
#include <stdint.h>
#include <math.h>

#define SEQ_L     200
#define EPS2      (1e-8f * 1e-8f)
#define VOCAB_MAX 100352
#define VROWS     96
#define VNT       192          // 6 warps; threads 0-95 chunk 0, 96-191 chunk 1

// Per-vocab precomputed table: (a0, a0*wd0, a1, a1*wd1)
__device__ float4 g_vtab[VOCAB_MAX];
// Monotonic barrier counters (never reset; ticket % grid identifies the round).
__device__ unsigned long long g_bar[2];

__device__ __forceinline__ uint32_t smem_u32(const void* p) {
    return (uint32_t)__cvta_generic_to_shared(p);
}

__device__ __forceinline__ void mbar_wait(uint32_t mb, uint32_t par) {
    uint32_t done;
    do {
        asm volatile(
            "{\n\t.reg .pred p;\n\t"
            "mbarrier.try_wait.parity.shared.b64 p, [%1], %2;\n\t"
            "selp.b32 %0, 1, 0, p;\n\t}"
            : "=r"(done) : "r"(mb), "r"(par) : "memory");
    } while (!done);
}

// Device-wide barrier: one arrival per block; deterministic across graph replays.
__device__ __forceinline__ void gbar(int k, unsigned int G) {
    __syncthreads();
    if (threadIdx.x == 0) {
        __threadfence();
        unsigned long long ticket = atomicAdd(&g_bar[k], 1ULL);
        unsigned long long target = ticket - (ticket % G) + G;
        while (*(volatile unsigned long long*)&g_bar[k] < target)
            __nanosleep(64);
        __threadfence();
    }
    __syncthreads();
}

__device__ __forceinline__ void tma_tile(uint32_t mb, const float4* sv,
                                         const float* emb, int r0, int nrows) {
    const unsigned int nbytes = (unsigned int)nrows * 400u;
    asm volatile("mbarrier.arrive.expect_tx.shared.b64 _, [%0], %1;"
                 :: "r"(mb), "r"(nbytes) : "memory");
    asm volatile("cp.async.bulk.shared::cta.global.mbarrier::complete_tx::bytes "
                 "[%0], [%1], %2, [%3];"
                 :: "r"(smem_u32(sv)), "l"(emb + (size_t)r0 * 100),
                    "r"(nbytes), "r"(mb) : "memory");
}

__device__ __forceinline__ void vtab_tile(const float4* sv, const float4* su,
                                          const float4* sw, int r0, int nrows, int t) {
    const int c   = t / VROWS;
    const int row = t - c * VROWS;
    if (row >= nrows) return;

    const float4* vp = sv + row * 25 + (c ? 13 : 0);
    const float4* up = su + (c ? 13 : 0);
    const float4* wp = sw + (c ? 13 : 0);

    float s = 0.f, d = 0.f, wd = 0.f, uu = 0.f;
    #pragma unroll
    for (int j = 0; j < 12; j++) {
        const float4 v = vp[j];
        const float4 u = up[j];     // warp-uniform broadcast
        const float4 q = wp[j];
        s  = fmaf(v.x, v.x, fmaf(v.y, v.y, fmaf(v.z, v.z, fmaf(v.w, v.w, s))));
        d  = fmaf(v.x, u.x, fmaf(v.y, u.y, fmaf(v.z, u.z, fmaf(v.w, u.w, d))));
        wd = fmaf(v.x, q.x, fmaf(v.y, q.y, fmaf(v.z, q.z, fmaf(v.w, q.w, wd))));
        uu = fmaf(u.x, u.x, fmaf(u.y, u.y, fmaf(u.z, u.z, fmaf(u.w, u.w, uu))));
    }
    // Boundary float4 #12 (floats 48-51): x,y -> chunk 0; z,w -> chunk 1.
    const float4 vb = sv[row * 25 + 12];
    const float4 ub = su[12];
    const float4 qb = sw[12];
    const float ex = c ? vb.z : vb.x,  ey = c ? vb.w : vb.y;
    const float ux = c ? ub.z : ub.x,  uy = c ? ub.w : ub.y;
    const float wx = c ? qb.z : qb.x,  wy = c ? qb.w : qb.y;
    s  = fmaf(ex, ex, fmaf(ey, ey, s));
    d  = fmaf(ex, ux, fmaf(ey, uy, d));
    wd = fmaf(ex, wx, fmaf(ey, wy, wd));
    uu = fmaf(ux, ux, fmaf(uy, uy, uu));

    const float a = __expf(d * rsqrtf(fmaxf(s, EPS2)) * rsqrtf(fmaxf(uu, EPS2)));
    float2* dst = (float2*)((float*)&g_vtab[r0 + row] + 2 * c);
    *dst = make_float2(a, a * wd);
}

#define GATHER4(i4, COND)                                         \
    do {                                                          \
        if ((i4).x COND) { const float4 v = __ldg(&g_vtab[(i4).x]); \
            A0 += v.x; P0 += v.y; A1 += v.z; P1 += v.w; }         \
        if ((i4).y COND) { const float4 v = __ldg(&g_vtab[(i4).y]); \
            A0 += v.x; P0 += v.y; A1 += v.z; P1 += v.w; }         \
        if ((i4).z COND) { const float4 v = __ldg(&g_vtab[(i4).z]); \
            A0 += v.x; P0 += v.y; A1 += v.z; P1 += v.w; }         \
        if ((i4).w COND) { const float4 v = __ldg(&g_vtab[(i4).w]); \
            A0 += v.x; P0 += v.y; A1 += v.z; P1 += v.w; }         \
    } while (0)

__global__ __launch_bounds__(VNT, 5)
void binclf_fused(const int*   __restrict__ word_idxs,   // [B, 200]
                  const float* __restrict__ emb_table,   // [vocab, 100]
                  const float* __restrict__ weights,     // [100]
                  const float* __restrict__ attend_u,    // [100] chunk-major
                  float*       __restrict__ out,         // [B]
                  int B, int vocab)
{
    __shared__ float4 sv[VROWS * 25];   // 38400 B
    __shared__ float4 su[25];
    __shared__ float4 sw[25];
    __shared__ __align__(8) unsigned long long mbar;

    const int t    = threadIdx.x;
    const int lane = t & 31;
    const int w    = t >> 5;
    const int bid  = blockIdx.x;
    const unsigned int G = gridDim.x;

    const int ntiles = (vocab + VROWS - 1) / VROWS;
    const int H      = (ntiles + 1) / 2;
    const int V2     = min(H * VROWS, vocab);
    const int nwarps = (int)G * (VNT / 32);
    const int gw     = bid * (VNT / 32) + w;

    if (t < 25)                 su[t]      = ((const float4*)attend_u)[t];
    else if (t >= 32 && t < 57) sw[t - 32] = ((const float4*)weights)[t - 32];

    const uint32_t mb = smem_u32(&mbar);
    if (t == 0)
        asm volatile("mbarrier.init.shared.b64 [%0], %1;" :: "r"(mb), "r"(1) : "memory");
    __syncthreads();
    uint32_t par = 0;

    // ---- Owned tasks (one batch row per warp) + idx preload into registers ----
    int  tb[2] = {-1, -1};
    int4 ia[2], ib[2];
    int  ntask = 0;
    for (int b = gw; b < B && ntask < 2; b += nwarps) tb[ntask++] = b;
    if (lane < 25) {
        for (int k = 0; k < ntask; k++) {
            const int4* rp = (const int4*)(word_idxs + (size_t)tb[k] * SEQ_L);
            ia[k] = __ldg(rp + 2 * lane);
            ib[k] = __ldg(rp + 2 * lane + 1);
        }
    }

    // ---- P0: stream vocab half 1 into g_vtab ----
    for (int tile = bid; tile < H; tile += G) {
        const int r0 = tile * VROWS;
        const int nr = min(VROWS, vocab - r0);
        if (t == 0) tma_tile(mb, sv, emb_table, r0, nr);
        mbar_wait(mb, par); par ^= 1;
        __syncthreads();
        vtab_tile(sv, su, sw, r0, nr, t);
        __syncthreads();
    }

    // Issue this block's first P1 tile before the barrier (overlaps spin + gathers).
    const int tile1  = H + bid;
    const bool havet = (tile1 < ntiles);
    const int r1 = tile1 * VROWS;
    const int n1 = havet ? min(VROWS, vocab - r1) : 0;
    if (havet && t == 0) tma_tile(mb, sv, emb_table, r1, n1);

    gbar(0, G);

    // ---- P1: gather idx < V2 while the half-2 TMA streams ----
    float A0[2] = {0.f, 0.f}, P0[2] = {0.f, 0.f};
    float A1[2] = {0.f, 0.f}, P1[2] = {0.f, 0.f};
    if (lane < 25) {
        for (int k = 0; k < ntask; k++) {
            float A0_ = 0.f, P0_ = 0.f, A1_ = 0.f, P1_ = 0.f;
            { float &A0 = A0_, &P0 = P0_, &A1 = A1_, &P1 = P1_;
              GATHER4(ia[k], < V2); GATHER4(ib[k], < V2); }
            A0[k] = A0_; P0[k] = P0_; A1[k] = A1_; P1[k] = P1_;
        }
    }

    if (havet) {
        mbar_wait(mb, par); par ^= 1;
        __syncthreads();
        vtab_tile(sv, su, sw, r1, n1, t);
        __syncthreads();
    }
    // Rare extra tiles (grid smaller than tile count): fully serial.
    for (int tile = tile1 + G; tile < ntiles; tile += G) {
        const int r0 = tile * VROWS;
        const int nr = min(VROWS, vocab - r0);
        if (t == 0) tma_tile(mb, sv, emb_table, r0, nr);
        mbar_wait(mb, par); par ^= 1;
        __syncthreads();
        vtab_tile(sv, su, sw, r0, nr, t);
        __syncthreads();
    }

    gbar(1, G);

    // ---- P2: gather idx >= V2, reduce, write ----
    for (int k = 0; k < ntask; k++) {
        float A0_ = A0[k], P0_ = P0[k], A1_ = A1[k], P1_ = P1[k];
        if (lane < 25) {
            float &A0 = A0_, &P0 = P0_, &A1 = A1_, &P1 = P1_;
            GATHER4(ia[k], >= V2); GATHER4(ib[k], >= V2);
        }
        #pragma unroll
        for (int o = 16; o > 0; o >>= 1) {
            A0_ += __shfl_xor_sync(0xffffffffu, A0_, o);
            P0_ += __shfl_xor_sync(0xffffffffu, P0_, o);
            A1_ += __shfl_xor_sync(0xffffffffu, A1_, o);
            P1_ += __shfl_xor_sync(0xffffffffu, P1_, o);
        }
        if (lane == 0)
            out[tb[k]] = P0_ / A0_ + P1_ / A1_;
    }

    // Fallback for B > 2*nwarps (not hit at B=4096, grid>=342): full gather now.
    for (int b = gw + 2 * nwarps; b < B; b += nwarps) {
        float A0_ = 0.f, P0_ = 0.f, A1_ = 0.f, P1_ = 0.f;
        if (lane < 25) {
            const int4* rp = (const int4*)(word_idxs + (size_t)b * SEQ_L);
            const int4 x = __ldg(rp + 2 * lane);
            const int4 y = __ldg(rp + 2 * lane + 1);
            float &A0 = A0_, &P0 = P0_, &A1 = A1_, &P1 = P1_;
            GATHER4(x, >= 0); GATHER4(y, >= 0);
        }
        #pragma unroll
        for (int o = 16; o > 0; o >>= 1) {
            A0_ += __shfl_xor_sync(0xffffffffu, A0_, o);
            P0_ += __shfl_xor_sync(0xffffffffu, P0_, o);
            A1_ += __shfl_xor_sync(0xffffffffu, A1_, o);
            P1_ += __shfl_xor_sync(0xffffffffu, P1_, o);
        }
        if (lane == 0)
            out[b] = P0_ / A0_ + P1_ / A1_;
    }
}

extern "C" void kernel_launch(void* const* d_in, const int* in_sizes, int n_in,
                              void* d_out, int out_size)
{
    const int*   word_idxs = (const int*)  d_in[0];  // [B, 200] int32
    const float* emb_table = (const float*)d_in[1];  // [vocab, 100] f32
    const float* weights   = (const float*)d_in[2];  // [100, 1] f32
    const float* attend_u  = (const float*)d_in[3];  // [2, 50] f32
    float*       out       = (float*)d_out;          // [B] f32

    const int B     = in_sizes[0] / SEQ_L;
    const int vocab = in_sizes[1] / 100;

    // Grid = exactly one resident wave (device-wide barrier requires full residency).
    cudaFuncSetAttribute(binclf_fused,
                         cudaFuncAttributePreferredSharedMemoryCarveout, 100);
    int dev = 0, sms = 148, occ = 1;
    cudaGetDevice(&dev);
    cudaDeviceGetAttribute(&sms, cudaDevAttrMultiProcessorCount, dev);
    cudaOccupancyMaxActiveBlocksPerMultiprocessor(&occ, binclf_fused, VNT, 0);
    if (occ < 1) occ = 1;
    int grid = occ * sms;

    binclf_fused<<<grid, VNT>>>(word_idxs, emb_table, weights, attend_u,
                                out, B, vocab);
}

// round 15
// speedup vs baseline: 1.4788x; 1.4788x over previous
#include <cuda_runtime.h>
#include <stdint.h>
#include <math.h>

#define SEQ_L     200
#define EPS2      (1e-8f * 1e-8f)
#define VOCAB_MAX 100352
#define VROWS     64
#define VNT       128      // one thread per (row, chunk): 64 rows x 2 chunks

// Per-vocab precomputed table: (a0, a0*wd0, a1, a1*wd1)
__device__ float4 g_vtab[VOCAB_MAX];

__device__ __forceinline__ uint32_t smem_u32(const void* p) {
    return (uint32_t)__cvta_generic_to_shared(p);
}

__device__ __forceinline__ void mbar_wait(uint32_t mb, uint32_t par) {
    uint32_t done;
    do {
        asm volatile(
            "{\n\t.reg .pred p;\n\t"
            "mbarrier.try_wait.parity.acquire.cta.shared::cta.b64 p, [%1], %2;\n\t"
            "selp.b32 %0, 1, 0, p;\n\t}"
            : "=r"(done) : "r"(mb), "r"(par) : "memory");
    } while (!done);
}

__device__ __forceinline__ void tma_tile(uint32_t mb, const float4* dst,
                                         const float* emb, int r0, int nrows) {
    const unsigned int nbytes = (unsigned int)nrows * 400u;
    asm volatile("mbarrier.arrive.expect_tx.shared.b64 _, [%0], %1;"
                 :: "r"(mb), "r"(nbytes) : "memory");
    asm volatile("cp.async.bulk.shared::cta.global.mbarrier::complete_tx::bytes "
                 "[%0], [%1], %2, [%3];"
                 :: "r"(smem_u32(dst)), "l"(emb + (size_t)r0 * 100),
                    "r"(nbytes), "r"(mb) : "memory");
}

// ---- Kernel 1: per-vocab precompute, grid-strided tiles, ping-pong TMA ----
__global__ __launch_bounds__(VNT, 4)
void binclf_vtab(const float* __restrict__ emb_table,   // [vocab, 100]
                 const float* __restrict__ weights,     // [100]
                 const float* __restrict__ attend_u,    // [100] chunk-major
                 int vocab)
{
    __shared__ float4 sv[2][VROWS * 25];   // 2 x 25600 B, stride 25 f4 (conflict-free)
    __shared__ float4 su[25];
    __shared__ float4 sw[25];
    __shared__ __align__(8) unsigned long long mbar[2];

    const int t   = threadIdx.x;
    const int bid = blockIdx.x;
    const unsigned int G = gridDim.x;
    const int ntiles = (vocab + VROWS - 1) / VROWS;

    if (t < 25)                 su[t]      = ((const float4*)attend_u)[t];
    else if (t >= 32 && t < 57) sw[t - 32] = ((const float4*)weights)[t - 32];

    const uint32_t mb0 = smem_u32(&mbar[0]);
    const uint32_t mb1 = smem_u32(&mbar[1]);
    if (t == 0) {
        asm volatile("mbarrier.init.shared.b64 [%0], 1;" :: "r"(mb0) : "memory");
        asm volatile("mbarrier.init.shared.b64 [%0], 1;" :: "r"(mb1) : "memory");
    }
    __syncthreads();

    // Prime buffer 0 with this block's first tile.
    if (bid < ntiles && t == 0) {
        const int r0 = bid * VROWS;
        tma_tile(mb0, sv[0], emb_table, r0, min(VROWS, vocab - r0));
    }

    uint32_t phase[2] = {0, 0};
    int i = 0;
    for (int tile = bid; tile < ntiles; tile += G, i++) {
        const int buf = i & 1;
        // Prefetch next tile into the other buffer (consumed & synced last iter).
        const int ntile = tile + G;
        if (ntile < ntiles && t == 0) {
            const int r0 = ntile * VROWS;
            tma_tile(buf ? mb0 : mb1, sv[buf ^ 1], emb_table, r0,
                     min(VROWS, vocab - r0));
        }

        mbar_wait(buf ? mb1 : mb0, phase[buf]);
        phase[buf] ^= 1;

        // One thread per (row, chunk): t<64 chunk 0, t>=64 chunk 1.
        const int r0    = tile * VROWS;
        const int nrows = min(VROWS, vocab - r0);
        const int c     = t >> 6;
        const int row   = t & 63;
        if (row < nrows) {
            const float4* vp = sv[buf] + row * 25 + (c ? 13 : 0);
            const float4* up = su + (c ? 13 : 0);
            const float4* wp = sw + (c ? 13 : 0);

            float s = 0.f, d = 0.f, wd = 0.f, uu = 0.f;
            #pragma unroll
            for (int j = 0; j < 12; j++) {
                const float4 v = vp[j];
                const float4 u = up[j];     // warp-uniform broadcast
                const float4 q = wp[j];
                s  = fmaf(v.x, v.x, fmaf(v.y, v.y, fmaf(v.z, v.z, fmaf(v.w, v.w, s))));
                d  = fmaf(v.x, u.x, fmaf(v.y, u.y, fmaf(v.z, u.z, fmaf(v.w, u.w, d))));
                wd = fmaf(v.x, q.x, fmaf(v.y, q.y, fmaf(v.z, q.z, fmaf(v.w, q.w, wd))));
                uu = fmaf(u.x, u.x, fmaf(u.y, u.y, fmaf(u.z, u.z, fmaf(u.w, u.w, uu))));
            }
            // Boundary float4 #12 (floats 48-51): x,y -> chunk 0; z,w -> chunk 1.
            const float4 vb = sv[buf][row * 25 + 12];
            const float4 ub = su[12];
            const float4 qb = sw[12];
            const float ex = c ? vb.z : vb.x,  ey = c ? vb.w : vb.y;
            const float ux = c ? ub.z : ub.x,  uy = c ? ub.w : ub.y;
            const float wx = c ? qb.z : qb.x,  wy = c ? qb.w : qb.y;
            s  = fmaf(ex, ex, fmaf(ey, ey, s));
            d  = fmaf(ex, ux, fmaf(ey, uy, d));
            wd = fmaf(ex, wx, fmaf(ey, wy, wd));
            uu = fmaf(ux, ux, fmaf(uy, uy, uu));

            const float a = __expf(d * rsqrtf(fmaxf(s, EPS2))
                                     * rsqrtf(fmaxf(uu, EPS2)));
            float2* dst = (float2*)((float*)&g_vtab[r0 + row] + 2 * c);
            *dst = make_float2(a, a * wd);
        }
        __syncthreads();   // buffer fully consumed before next-iter prefetch reuses it
    }

    cudaTriggerProgrammaticLaunchCompletion();
}

// ---- Kernel 2 (PDL secondary): idx preload overlaps vtab's tail, then gather ----
__global__ __launch_bounds__(256)
void binclf_accum(const int* __restrict__ word_idxs,    // [B, 200]
                  float*     __restrict__ out,          // [B]
                  int B)
{
    __shared__ float4 spart[8];

    const int t    = threadIdx.x;
    const int lane = t & 31;
    const int w    = t >> 5;
    const int b    = blockIdx.x * 4 + (w >> 1);
    const int sub  = w & 1;

    // Prologue: preload this warp's 100 word indices (independent of g_vtab).
    int4 idx = make_int4(-1, -1, -1, -1);
    if (b < B && lane < 25)
        idx = __ldg((const int4*)(word_idxs + (size_t)b * SEQ_L + sub * 100) + lane);

    // Wait for vtab's writes to be visible (all threads, uniform).
    cudaGridDependencySynchronize();

    float A0 = 0.f, P0 = 0.f, A1 = 0.f, P1 = 0.f;
    if (b < B) {
        if (idx.x >= 0) {
            const float4 v0 = __ldg(&g_vtab[idx.x]);
            const float4 v1 = __ldg(&g_vtab[idx.y]);
            const float4 v2 = __ldg(&g_vtab[idx.z]);
            const float4 v3 = __ldg(&g_vtab[idx.w]);
            A0 = v0.x + v1.x + v2.x + v3.x;
            P0 = v0.y + v1.y + v2.y + v3.y;
            A1 = v0.z + v1.z + v2.z + v3.z;
            P1 = v0.w + v1.w + v2.w + v3.w;
        }
        #pragma unroll
        for (int o = 16; o > 0; o >>= 1) {
            A0 += __shfl_xor_sync(0xffffffffu, A0, o);
            P0 += __shfl_xor_sync(0xffffffffu, P0, o);
            A1 += __shfl_xor_sync(0xffffffffu, A1, o);
            P1 += __shfl_xor_sync(0xffffffffu, P1, o);
        }
    }

    if (lane == 0) spart[w] = make_float4(A0, P0, A1, P1);
    __syncthreads();

    if (t < 4) {
        const int bb = blockIdx.x * 4 + t;
        if (bb < B) {
            const float4 x = spart[2 * t];
            const float4 y = spart[2 * t + 1];
            out[bb] = (x.y + y.y) / (x.x + y.x) + (x.w + y.w) / (x.z + y.z);
        }
    }
}

extern "C" void kernel_launch(void* const* d_in, const int* in_sizes, int n_in,
                              void* d_out, int out_size)
{
    const int*   word_idxs = (const int*)  d_in[0];  // [B, 200] int32
    const float* emb_table = (const float*)d_in[1];  // [vocab, 100] f32
    const float* weights   = (const float*)d_in[2];  // [100, 1] f32
    const float* attend_u  = (const float*)d_in[3];  // [2, 50] f32
    float*       out       = (float*)d_out;          // [B] f32

    const int B     = in_sizes[0] / SEQ_L;
    const int vocab = in_sizes[1] / 100;

    const int ntiles = (vocab + VROWS - 1) / VROWS;
    int dev = 0, sms = 148;
    cudaGetDevice(&dev);
    cudaDeviceGetAttribute(&sms, cudaDevAttrMultiProcessorCount, dev);
    int vgrid = 4 * sms;
    if (vgrid > ntiles) vgrid = ntiles;

    binclf_vtab<<<vgrid, VNT>>>(emb_table, weights, attend_u, vocab);

    // Secondary with programmatic dependent launch: starts during vtab's drain.
    cudaLaunchConfig_t cfg = {};
    cfg.gridDim  = dim3((B + 3) / 4, 1, 1);
    cfg.blockDim = dim3(256, 1, 1);
    cudaLaunchAttribute attr[1];
    attr[0].id = cudaLaunchAttributeProgrammaticStreamSerialization;
    attr[0].val.programmaticStreamSerializationAllowed = 1;
    cfg.attrs = attr;
    cfg.numAttrs = 1;
    cudaLaunchKernelEx(&cfg, binclf_accum, word_idxs, (float*)out, B);
}